// round 15
// baseline (speedup 1.0000x reference)
#include <cuda_runtime.h>
#include <cuda_bf16.h>
#include <cuda_fp16.h>
#include <stdint.h>
#include <math.h>

#define EMBED 512
#define HH    8
#define HD    64
#define NQ    2048
#define LK    2048
#define BB    4
#define MROWS (NQ * BB)
#define NELEM ((size_t)MROWS * EMBED)
#define WELEM ((size_t)EMBED * EMBED)

// ---------------- device scratch (allocation-free rule) --------------------
__device__ __align__(256) __half g_Xq[NELEM], g_Xk[NELEM], g_Xv[NELEM];
__device__ __align__(256) __half g_Wq[WELEM], g_Wk[WELEM];
__device__ __align__(256) __half g_Wv[WELEM], g_Wo[WELEM];
__device__ __align__(256) __half g_Qh[NELEM];    // [bh][n][64], x1/8
__device__ __align__(256) __half g_Kh[NELEM];    // [bh][l][64]
__device__ __align__(256) __half g_Vth[NELEM];   // [bh][d][L]
__device__ __align__(256) __half g_Ath[NELEM];   // [r][512]

// ---------------- helpers ---------------------------------------------------
__device__ __forceinline__ uint32_t smem_u32(const void* p) {
    uint32_t a;
    asm("{ .reg .u64 t; cvta.to.shared.u64 t, %1; cvt.u32.u64 %0, t; }"
        : "=r"(a) : "l"(p));
    return a;
}
__device__ __forceinline__ uint32_t pkh(float a, float b) {
    __half2 h = __floats2half2_rn(a, b);
    return *reinterpret_cast<uint32_t*>(&h);
}
__device__ __forceinline__ void mma16816h(float* c, const uint32_t* a,
                                          uint32_t b0, uint32_t b1) {
    asm volatile(
        "mma.sync.aligned.m16n8k16.row.col.f32.f16.f16.f32 "
        "{%0,%1,%2,%3}, {%4,%5,%6,%7}, {%8,%9}, {%0,%1,%2,%3};"
        : "+f"(c[0]), "+f"(c[1]), "+f"(c[2]), "+f"(c[3])
        : "r"(a[0]), "r"(a[1]), "r"(a[2]), "r"(a[3]), "r"(b0), "r"(b1));
}
__device__ __forceinline__ void ldsm4(uint32_t* r, uint32_t addr) {
    asm volatile("ldmatrix.sync.aligned.m8n8.x4.shared.b16 {%0,%1,%2,%3}, [%4];"
                 : "=r"(r[0]), "=r"(r[1]), "=r"(r[2]), "=r"(r[3]) : "r"(addr));
}
__device__ __forceinline__ void cpa16(uint32_t s, const void* g) {
    asm volatile("cp.async.cg.shared.global [%0], [%1], 16;" :: "r"(s), "l"(g));
}

// ---------------------------------------------------------------------------
// split kernels: everything -> single fp16
// ---------------------------------------------------------------------------
__global__ __launch_bounds__(256)
void splitX(const float* __restrict__ q, const float* __restrict__ k,
            const float* __restrict__ v,
            __half* xq, __half* xk, __half* xv)
{
    const float* src; __half* dst;
    if (blockIdx.y == 0)      { src = q; dst = xq; }
    else if (blockIdx.y == 1) { src = k; dst = xk; }
    else                      { src = v; dst = xv; }
    size_t i = (size_t)blockIdx.x * 256 + threadIdx.x;
    float4 x = ((const float4*)src)[i];
    ((uint2*)dst)[i] = make_uint2(pkh(x.x, x.y), pkh(x.z, x.w));
}

__global__ __launch_bounds__(256)
void splitW(const float* __restrict__ wq, const float* __restrict__ wk,
            const float* __restrict__ wv, const float* __restrict__ wo,
            __half* dq, __half* dk, __half* dv, __half* dw)
{
    const float* src; __half* dst;
    if (blockIdx.y == 0)      { src = wq; dst = dq; }
    else if (blockIdx.y == 1) { src = wk; dst = dk; }
    else if (blockIdx.y == 2) { src = wv; dst = dv; }
    else                      { src = wo; dst = dw; }
    size_t i = (size_t)blockIdx.x * 256 + threadIdx.x;
    float4 x = ((const float4*)src)[i];
    ((uint2*)dst)[i] = make_uint2(pkh(x.x, x.y), pkh(x.z, x.w));
}

// ---------------------------------------------------------------------------
// fp16 single x single GEMM core (unchanged from R14)
// ---------------------------------------------------------------------------
#define BKS   40
#define STG_A (128 * BKS)
#define STG_W (64 * BKS)
#define STG_TOT (STG_A + STG_W)
#define NSTG  3
#define GEMM_SMEM (NSTG * STG_TOT * 2)

__device__ __forceinline__ void gemm_core_h(
    const __half* __restrict__ A, const __half* __restrict__ W,
    int m0, int e0, uint32_t sb, int tid, float c[8][4])
{
    const int wid = tid >> 5, lane = tid & 31;
    const int wrow = wid * 16;
    const int aR = wrow + (lane & 7) + ((lane >> 3) & 1) * 8;
    const int aC = (lane >> 4) * 8;
    const int bR = lane & 7, bC = (lane >> 3) * 8;

    auto load_stage = [&](int s, int kk) {
        uint32_t bs_ = sb + s * (STG_TOT * 2);
#pragma unroll
        for (int ch = tid; ch < 512; ch += 256) {
            int r_ = ch >> 2, o_ = (ch & 3) * 8;
            cpa16(bs_ + (r_ * BKS + o_) * 2, A + (size_t)(m0 + r_) * 512 + kk + o_);
        }
        {
            int r_ = tid >> 2, o_ = (tid & 3) * 8;
            cpa16(bs_ + (STG_A + r_ * BKS + o_) * 2,
                  W + (size_t)(e0 + r_) * 512 + kk + o_);
        }
        asm volatile("cp.async.commit_group;");
    };

    load_stage(0, 0);
    load_stage(1, 32);

    int s_cur = 0, s_pref = 2;
    for (int kc = 0; kc < 16; kc++) {
        asm volatile("cp.async.wait_group 1;" ::: "memory");
        __syncthreads();
        if (kc + 2 < 16) { load_stage(s_pref, (kc + 2) * 32); }
        else { asm volatile("cp.async.commit_group;"); }
        if (++s_pref == NSTG) s_pref = 0;

        const uint32_t bs = sb + s_cur * (STG_TOT * 2);
        if (++s_cur == NSTG) s_cur = 0;

        uint32_t a0[4], a1[4];
        ldsm4(a0, bs + (aR * BKS + aC) * 2);
        ldsm4(a1, bs + (aR * BKS + 16 + aC) * 2);
#pragma unroll
        for (int j = 0; j < 8; j++) {
            uint32_t bh[4];
            ldsm4(bh, bs + (STG_A + (j * 8 + bR) * BKS + bC) * 2);
            mma16816h(c[j], a0, bh[0], bh[1]);
            mma16816h(c[j], a1, bh[2], bh[3]);
        }
    }
}

// ---------------------------------------------------------------------------
// Q/K/V projection GEMM (grid.z selects)
// ---------------------------------------------------------------------------
__global__ __launch_bounds__(256, 2)
void gemm_qkv(const __half* __restrict__ Xq, const __half* __restrict__ Xk,
              const __half* __restrict__ Xv,
              const __half* __restrict__ Wq, const __half* __restrict__ Wk,
              const __half* __restrict__ Wv,
              const float* __restrict__ bq, const float* __restrict__ bk,
              const float* __restrict__ bv,
              __half* Qh, __half* Kh, __half* Vth)
{
    extern __shared__ __half smg[];
    const uint32_t sb = smem_u32(smg);
    const int tid = threadIdx.x, wid = tid >> 5, lane = tid & 31;
    const int m0 = blockIdx.y * 128, e0 = blockIdx.x * 64;
    const int z = blockIdx.z;
    const int g = lane >> 2, t2 = (lane & 3) * 2;

    const __half *A, *W;
    const float* bias;
    if (z == 0)      { A = Xq; W = Wq; bias = bq; }
    else if (z == 1) { A = Xk; W = Wk; bias = bk; }
    else             { A = Xv; W = Wv; bias = bv; }

    float c[8][4];
#pragma unroll
    for (int j = 0; j < 8; j++)
#pragma unroll
        for (int e = 0; e < 4; e++) c[j][e] = 0.f;

    gemm_core_h(A, W, m0, e0, sb, tid, c);

    const int r0 = m0 + wid * 16 + g;
    const int hh = e0 >> 6;
    if (z < 2) {
        const float scale = (z == 0) ? 0.125f : 1.0f;
        const int nn0 = r0 >> 2, bb2 = r0 & 3;
        __half* H = (z == 0 ? Qh : Kh) + ((size_t)(bb2 * HH + hh) * NQ + nn0) * 64;
#pragma unroll
        for (int j = 0; j < 8; j++) {
            const int d = j * 8 + t2;
            const int e = e0 + d;
            float b0 = bias[e], b1 = bias[e + 1];
            float v0 = (c[j][0] + b0) * scale, v1 = (c[j][1] + b1) * scale;
            float v2 = (c[j][2] + b0) * scale, v3 = (c[j][3] + b1) * scale;
            *(uint32_t*)(H + d)          = pkh(v0, v1);
            *(uint32_t*)(H + 2 * 64 + d) = pkh(v2, v3);
        }
    } else {
        const int lv = r0 >> 2, bb2 = r0 & 3;
        __half* VH = Vth + (size_t)(bb2 * HH + hh) * HD * LK;
#pragma unroll
        for (int j = 0; j < 8; j++) {
            const int d = j * 8 + t2;
            float b0 = bias[e0 + d], b1 = bias[e0 + d + 1];
            float v0 = c[j][0] + b0, v1 = c[j][1] + b1;
            float v2 = c[j][2] + b0, v3 = c[j][3] + b1;
#pragma unroll
            for (int u = 0; u < 4; u++) {
                float val = (u == 0) ? v0 : (u == 1) ? v1 : (u == 2) ? v2 : v3;
                int dd = d + (u & 1);
                int ll = lv + ((u >> 1) * 2);
                VH[(size_t)dd * LK + ll] = __float2half_rn(val);
            }
        }
    }
}

// ---------------------------------------------------------------------------
// O projection GEMM (fp32 out, row-major)
// ---------------------------------------------------------------------------
__global__ __launch_bounds__(256, 2)
void gemm_o(const __half* __restrict__ A, const __half* __restrict__ W,
            const float* __restrict__ bias, float* __restrict__ Cf)
{
    extern __shared__ __half smg[];
    const uint32_t sb = smem_u32(smg);
    const int tid = threadIdx.x, wid = tid >> 5, lane = tid & 31;
    const int m0 = blockIdx.y * 128, e0 = blockIdx.x * 64;
    const int g = lane >> 2, t2 = (lane & 3) * 2;

    float c[8][4];
#pragma unroll
    for (int j = 0; j < 8; j++)
#pragma unroll
        for (int e = 0; e < 4; e++) c[j][e] = 0.f;

    gemm_core_h(A, W, m0, e0, sb, tid, c);

    const int r0 = m0 + wid * 16 + g, r8 = r0 + 8;
#pragma unroll
    for (int j = 0; j < 8; j++) {
        const int e = e0 + j * 8 + t2;
        float b0 = bias[e], b1 = bias[e + 1];
        *(float2*)(Cf + (size_t)r0 * 512 + e) = make_float2(c[j][0] + b0, c[j][1] + b1);
        *(float2*)(Cf + (size_t)r8 * 512 + e) = make_float2(c[j][2] + b0, c[j][3] + b1);
    }
}

// ---------------------------------------------------------------------------
// Flash attention, single-fp16, 32 q-rows/warp (two m16 blocks share every
// K/V fragment -> ldsm traffic per MMA halves). 2 warps/CTA (64 rows),
// __launch_bounds__(64, 5): 5 independent CTAs/SM.
// ---------------------------------------------------------------------------
#define KSTR 72
#define ASTG 19200   // per-stage: Kh (9216) | Vh (9216) | pe2 (768)
#define ATTN_SMEM (2 * ASTG)

__global__ __launch_bounds__(64, 5)
void attn_kernel(const float* __restrict__ pe1, const float* __restrict__ pe2)
{
    extern __shared__ char smc[];
    const uint32_t sb = smem_u32(smc);
    const int tid  = threadIdx.x;
    const int wid  = tid >> 5;           // 0..1
    const int lane = tid & 31;
    const int g    = lane >> 2;
    const int t2   = (lane & 3) * 2;
    const int bR   = lane & 7;
    const int bC   = (lane >> 3) * 8;
    const int bh   = blockIdx.y;
    const int b    = bh >> 3, h = bh & 7;
    const int n0   = blockIdx.x * 64;
    const int rowB = n0 + wid * 32;      // this warp's 32-row base

    // ---- Q fragments for two m16 row-blocks ----
    uint32_t qhA[4][4], qhB[4][4];
    {
        const __half* Qp = g_Qh + (size_t)bh * NQ * HD;
        const size_t rA0 = (size_t)(rowB + g) * HD;
        const size_t rA8 = (size_t)(rowB + g + 8) * HD;
        const size_t rB0 = (size_t)(rowB + g + 16) * HD;
        const size_t rB8 = (size_t)(rowB + g + 24) * HD;
#pragma unroll
        for (int ks = 0; ks < 4; ks++) {
            qhA[ks][0] = *(const uint32_t*)(Qp + rA0 + ks * 16 + t2);
            qhA[ks][1] = *(const uint32_t*)(Qp + rA8 + ks * 16 + t2);
            qhA[ks][2] = *(const uint32_t*)(Qp + rA0 + ks * 16 + 8 + t2);
            qhA[ks][3] = *(const uint32_t*)(Qp + rA8 + ks * 16 + 8 + t2);
            qhB[ks][0] = *(const uint32_t*)(Qp + rB0 + ks * 16 + t2);
            qhB[ks][1] = *(const uint32_t*)(Qp + rB8 + ks * 16 + t2);
            qhB[ks][2] = *(const uint32_t*)(Qp + rB0 + ks * 16 + 8 + t2);
            qhB[ks][3] = *(const uint32_t*)(Qp + rB8 + ks * 16 + 8 + t2);
        }
    }
    float p1[4][3];   // rows g, g+8, g+16, g+24 (scaled 1/8)
#pragma unroll
    for (int rr = 0; rr < 4; rr++)
#pragma unroll
        for (int cc = 0; cc < 3; cc++)
            p1[rr][cc] = pe1[((size_t)b * NQ + rowB + g + rr * 8) * 3 + cc] * 0.125f;

    float oA[8][4], oB[8][4];
#pragma unroll
    for (int j = 0; j < 8; j++)
#pragma unroll
        for (int e = 0; e < 4; e++) { oA[j][e] = 0.f; oB[j][e] = 0.f; }
    float rs[4] = {0.f, 0.f, 0.f, 0.f};

    auto issue_tile = [&](int l0, uint32_t stb) {
#pragma unroll
        for (int q8 = 0; q8 < 8; q8++) {
            int idx = tid + q8 * 64;             // 0..511
            int r = idx >> 3, cchunk = idx & 7;
            size_t ko = ((size_t)bh * LK + l0 + r) * HD + cchunk * 8;
            size_t vo = ((size_t)bh * HD + r) * LK + l0 + cchunk * 8;
            uint32_t so = stb + r * (KSTR * 2) + cchunk * 16;
            cpa16(so,        g_Kh + ko);
            cpa16(so + 9216, g_Vth + vo);
        }
        if (tid < 48)
            cpa16(stb + 18432 + tid * 16, (const char*)pe2 + (size_t)l0 * 12 + tid * 16);
        asm volatile("cp.async.commit_group;");
    };

    issue_tile(0, sb);

    for (int lt = 0; lt < LK / 64; lt++) {
        const int stcur = lt & 1;
        if (lt < LK / 64 - 1) {
            issue_tile((lt + 1) * 64, sb + ((lt + 1) & 1) * ASTG);
            asm volatile("cp.async.wait_group 1;" ::: "memory");
        } else {
            asm volatile("cp.async.wait_group 0;" ::: "memory");
        }
        __syncthreads();

        const uint32_t stb = sb + stcur * ASTG;
        const uint32_t uKh = stb, uVh = stb + 9216;
        const float* sp2 = (const float*)(smc + stcur * ASTG + 18432);

        // ---- S = Qh·Kh + pe1·pe2 (both row-blocks share each K fragment) ----
        float sA[8][4], sB[8][4];
#pragma unroll
        for (int j = 0; j < 8; j++) {
            const int jc = j * 8 + t2;
            float e0 = sp2[jc * 3 + 0], e1 = sp2[jc * 3 + 1], e2 = sp2[jc * 3 + 2];
            float f0 = sp2[(jc + 1) * 3 + 0], f1 = sp2[(jc + 1) * 3 + 1], f2 = sp2[(jc + 1) * 3 + 2];
            sA[j][0] = p1[0][0] * e0 + p1[0][1] * e1 + p1[0][2] * e2;
            sA[j][1] = p1[0][0] * f0 + p1[0][1] * f1 + p1[0][2] * f2;
            sA[j][2] = p1[1][0] * e0 + p1[1][1] * e1 + p1[1][2] * e2;
            sA[j][3] = p1[1][0] * f0 + p1[1][1] * f1 + p1[1][2] * f2;
            sB[j][0] = p1[2][0] * e0 + p1[2][1] * e1 + p1[2][2] * e2;
            sB[j][1] = p1[2][0] * f0 + p1[2][1] * f1 + p1[2][2] * f2;
            sB[j][2] = p1[3][0] * e0 + p1[3][1] * e1 + p1[3][2] * e2;
            sB[j][3] = p1[3][0] * f0 + p1[3][1] * f1 + p1[3][2] * f2;

            uint32_t kh[8];
            const uint32_t rb = (uint32_t)((j * 8 + bR) * KSTR + bC) * 2;
            ldsm4(kh,     uKh + rb);
            ldsm4(kh + 4, uKh + rb + 64);
#pragma unroll
            for (int ks = 0; ks < 4; ks++) {
                mma16816h(sA[j], qhA[ks], kh[2 * ks], kh[2 * ks + 1]);
                mma16816h(sB[j], qhB[ks], kh[2 * ks], kh[2 * ks + 1]);
            }
        }

        // ---- softmax (no max subtraction; scores bounded) ----
#pragma unroll
        for (int j = 0; j < 8; j++) {
            sA[j][0] = __expf(sA[j][0]); sA[j][1] = __expf(sA[j][1]);
            sA[j][2] = __expf(sA[j][2]); sA[j][3] = __expf(sA[j][3]);
            sB[j][0] = __expf(sB[j][0]); sB[j][1] = __expf(sB[j][1]);
            sB[j][2] = __expf(sB[j][2]); sB[j][3] = __expf(sB[j][3]);
            rs[0] += sA[j][0] + sA[j][1];
            rs[1] += sA[j][2] + sA[j][3];
            rs[2] += sB[j][0] + sB[j][1];
            rs[3] += sB[j][2] + sB[j][3];
        }

        // ---- P fragments (single fp16) ----
        uint32_t phA[4][4], phB[4][4];
#pragma unroll
        for (int ks = 0; ks < 4; ks++) {
            phA[ks][0] = pkh(sA[2 * ks][0], sA[2 * ks][1]);
            phA[ks][1] = pkh(sA[2 * ks][2], sA[2 * ks][3]);
            phA[ks][2] = pkh(sA[2 * ks + 1][0], sA[2 * ks + 1][1]);
            phA[ks][3] = pkh(sA[2 * ks + 1][2], sA[2 * ks + 1][3]);
            phB[ks][0] = pkh(sB[2 * ks][0], sB[2 * ks][1]);
            phB[ks][1] = pkh(sB[2 * ks][2], sB[2 * ks][3]);
            phB[ks][2] = pkh(sB[2 * ks + 1][0], sB[2 * ks + 1][1]);
            phB[ks][3] = pkh(sB[2 * ks + 1][2], sB[2 * ks + 1][3]);
        }

        // ---- O += Ph·Vh (both row-blocks share each V fragment) ----
#pragma unroll
        for (int j = 0; j < 8; j++) {
            uint32_t vh[8];
            const uint32_t rb = (uint32_t)((j * 8 + bR) * KSTR + bC) * 2;
            ldsm4(vh,     uVh + rb);
            ldsm4(vh + 4, uVh + rb + 64);
#pragma unroll
            for (int ks = 0; ks < 4; ks++) {
                mma16816h(oA[j], phA[ks], vh[2 * ks], vh[2 * ks + 1]);
                mma16816h(oB[j], phB[ks], vh[2 * ks], vh[2 * ks + 1]);
            }
        }
        __syncthreads();
    }

    // ---- epilogue: reduce 4 row-sums across the 4 lanes of each group ----
#pragma unroll
    for (int rr = 0; rr < 4; rr++) {
        rs[rr] += __shfl_xor_sync(0xffffffffu, rs[rr], 1);
        rs[rr] += __shfl_xor_sync(0xffffffffu, rs[rr], 2);
    }
    const float i0 = 1.f / rs[0], i8 = 1.f / rs[1];
    const float i16 = 1.f / rs[2], i24 = 1.f / rs[3];

    const size_t d0  = ((size_t)(rowB + g)      * BB + b) * EMBED + h * HD + t2;
    const size_t d8  = ((size_t)(rowB + g + 8)  * BB + b) * EMBED + h * HD + t2;
    const size_t d16 = ((size_t)(rowB + g + 16) * BB + b) * EMBED + h * HD + t2;
    const size_t d24 = ((size_t)(rowB + g + 24) * BB + b) * EMBED + h * HD + t2;
#pragma unroll
    for (int j = 0; j < 8; j++) {
        *(uint32_t*)(g_Ath + d0  + j * 8) = pkh(oA[j][0] * i0,  oA[j][1] * i0);
        *(uint32_t*)(g_Ath + d8  + j * 8) = pkh(oA[j][2] * i8,  oA[j][3] * i8);
        *(uint32_t*)(g_Ath + d16 + j * 8) = pkh(oB[j][0] * i16, oB[j][1] * i16);
        *(uint32_t*)(g_Ath + d24 + j * 8) = pkh(oB[j][2] * i24, oB[j][3] * i24);
    }
}

// ---------------------------------------------------------------------------
extern "C" void kernel_launch(void* const* d_in, const int* in_sizes, int n_in,
                              void* d_out, int out_size)
{
    const float* q   = (const float*)d_in[0];
    const float* k   = (const float*)d_in[1];
    const float* v   = (const float*)d_in[2];
    const float* pe1 = (const float*)d_in[3];
    const float* pe2 = (const float*)d_in[4];
    const float* Wq  = (const float*)d_in[5];
    const float* bq  = (const float*)d_in[6];
    const float* Wk  = (const float*)d_in[7];
    const float* bk  = (const float*)d_in[8];
    const float* Wv  = (const float*)d_in[9];
    const float* bv  = (const float*)d_in[10];
    const float* Wo  = (const float*)d_in[11];
    const float* bo  = (const float*)d_in[12];
    float* out = (float*)d_out;

    cudaFuncSetAttribute(gemm_qkv, cudaFuncAttributeMaxDynamicSharedMemorySize, GEMM_SMEM);
    cudaFuncSetAttribute(gemm_o, cudaFuncAttributeMaxDynamicSharedMemorySize, GEMM_SMEM);
    cudaFuncSetAttribute(attn_kernel, cudaFuncAttributeMaxDynamicSharedMemorySize, ATTN_SMEM);

    __half *Xq, *Xk, *Xv, *hWq, *hWk, *hWv, *hWo;
    __half *Qh, *Kh, *Vth, *Ath;
    cudaGetSymbolAddress((void**)&Xq, g_Xq);
    cudaGetSymbolAddress((void**)&Xk, g_Xk);
    cudaGetSymbolAddress((void**)&Xv, g_Xv);
    cudaGetSymbolAddress((void**)&hWq, g_Wq);
    cudaGetSymbolAddress((void**)&hWk, g_Wk);
    cudaGetSymbolAddress((void**)&hWv, g_Wv);
    cudaGetSymbolAddress((void**)&hWo, g_Wo);
    cudaGetSymbolAddress((void**)&Qh, g_Qh);
    cudaGetSymbolAddress((void**)&Kh, g_Kh);
    cudaGetSymbolAddress((void**)&Vth, g_Vth);
    cudaGetSymbolAddress((void**)&Ath, g_Ath);

    splitX<<<dim3(4096, 3), 256>>>(q, k, v, Xq, Xk, Xv);                            // 1
    splitW<<<dim3(256, 4), 256>>>(Wq, Wk, Wv, Wo, hWq, hWk, hWv, hWo);              // 2
    gemm_qkv<<<dim3(8, 64, 3), 256, GEMM_SMEM>>>(
        Xq, Xk, Xv, hWq, hWk, hWv, bq, bk, bv, Qh, Kh, Vth);                        // 3
    attn_kernel<<<dim3(32, 32), 64, ATTN_SMEM>>>(pe1, pe2);                         // 4 (profiled)
    gemm_o<<<dim3(8, 64), 256, GEMM_SMEM>>>(Ath, hWo, bo, out);                     // 5
}

// round 16
// speedup vs baseline: 1.0230x; 1.0230x over previous
#include <cuda_runtime.h>
#include <cuda_bf16.h>
#include <cuda_fp16.h>
#include <stdint.h>
#include <math.h>

#define EMBED 512
#define HH    8
#define HD    64
#define NQ    2048
#define LK    2048
#define BB    4
#define MROWS (NQ * BB)
#define NELEM ((size_t)MROWS * EMBED)
#define WELEM ((size_t)EMBED * EMBED)

// ---------------- device scratch (allocation-free rule) --------------------
__device__ __align__(256) __half g_Xq[NELEM], g_Xk[NELEM], g_Xv[NELEM];
__device__ __align__(256) __half g_Wq[WELEM], g_Wk[WELEM];
__device__ __align__(256) __half g_Wv[WELEM], g_Wo[WELEM];
__device__ __align__(256) __half g_Qh[NELEM];    // [bh][n][64], x1/8
__device__ __align__(256) __half g_Kh[NELEM];    // [bh][l][64]
__device__ __align__(256) __half g_Vth[NELEM];   // [bh][d][L]
__device__ __align__(256) __half g_Ath[NELEM];   // [r][512]

// ---------------- helpers ---------------------------------------------------
__device__ __forceinline__ uint32_t smem_u32(const void* p) {
    uint32_t a;
    asm("{ .reg .u64 t; cvta.to.shared.u64 t, %1; cvt.u32.u64 %0, t; }"
        : "=r"(a) : "l"(p));
    return a;
}
__device__ __forceinline__ uint32_t pkh(float a, float b) {
    __half2 h = __floats2half2_rn(a, b);
    return *reinterpret_cast<uint32_t*>(&h);
}
__device__ __forceinline__ void mma16816h(float* c, const uint32_t* a,
                                          uint32_t b0, uint32_t b1) {
    asm volatile(
        "mma.sync.aligned.m16n8k16.row.col.f32.f16.f16.f32 "
        "{%0,%1,%2,%3}, {%4,%5,%6,%7}, {%8,%9}, {%0,%1,%2,%3};"
        : "+f"(c[0]), "+f"(c[1]), "+f"(c[2]), "+f"(c[3])
        : "r"(a[0]), "r"(a[1]), "r"(a[2]), "r"(a[3]), "r"(b0), "r"(b1));
}
__device__ __forceinline__ void ldsm4(uint32_t* r, uint32_t addr) {
    asm volatile("ldmatrix.sync.aligned.m8n8.x4.shared.b16 {%0,%1,%2,%3}, [%4];"
                 : "=r"(r[0]), "=r"(r[1]), "=r"(r[2]), "=r"(r[3]) : "r"(addr));
}
__device__ __forceinline__ void cpa16(uint32_t s, const void* g) {
    asm volatile("cp.async.cg.shared.global [%0], [%1], 16;" :: "r"(s), "l"(g));
}

// ---------------------------------------------------------------------------
// split kernels: everything -> single fp16
// ---------------------------------------------------------------------------
__global__ __launch_bounds__(256)
void splitX(const float* __restrict__ q, const float* __restrict__ k,
            const float* __restrict__ v,
            __half* xq, __half* xk, __half* xv)
{
    const float* src; __half* dst;
    if (blockIdx.y == 0)      { src = q; dst = xq; }
    else if (blockIdx.y == 1) { src = k; dst = xk; }
    else                      { src = v; dst = xv; }
    size_t i = (size_t)blockIdx.x * 256 + threadIdx.x;
    float4 x = ((const float4*)src)[i];
    ((uint2*)dst)[i] = make_uint2(pkh(x.x, x.y), pkh(x.z, x.w));
}

__global__ __launch_bounds__(256)
void splitW(const float* __restrict__ wq, const float* __restrict__ wk,
            const float* __restrict__ wv, const float* __restrict__ wo,
            __half* dq, __half* dk, __half* dv, __half* dw)
{
    const float* src; __half* dst;
    if (blockIdx.y == 0)      { src = wq; dst = dq; }
    else if (blockIdx.y == 1) { src = wk; dst = dk; }
    else if (blockIdx.y == 2) { src = wv; dst = dv; }
    else                      { src = wo; dst = dw; }
    size_t i = (size_t)blockIdx.x * 256 + threadIdx.x;
    float4 x = ((const float4*)src)[i];
    ((uint2*)dst)[i] = make_uint2(pkh(x.x, x.y), pkh(x.z, x.w));
}

// ---------------------------------------------------------------------------
// fp16 single x single GEMM core (unchanged)
// ---------------------------------------------------------------------------
#define BKS   40
#define STG_A (128 * BKS)
#define STG_W (64 * BKS)
#define STG_TOT (STG_A + STG_W)
#define NSTG  3
#define GEMM_SMEM (NSTG * STG_TOT * 2)

__device__ __forceinline__ void gemm_core_h(
    const __half* __restrict__ A, const __half* __restrict__ W,
    int m0, int e0, uint32_t sb, int tid, float c[8][4])
{
    const int wid = tid >> 5, lane = tid & 31;
    const int wrow = wid * 16;
    const int aR = wrow + (lane & 7) + ((lane >> 3) & 1) * 8;
    const int aC = (lane >> 4) * 8;
    const int bR = lane & 7, bC = (lane >> 3) * 8;

    auto load_stage = [&](int s, int kk) {
        uint32_t bs_ = sb + s * (STG_TOT * 2);
#pragma unroll
        for (int ch = tid; ch < 512; ch += 256) {
            int r_ = ch >> 2, o_ = (ch & 3) * 8;
            cpa16(bs_ + (r_ * BKS + o_) * 2, A + (size_t)(m0 + r_) * 512 + kk + o_);
        }
        {
            int r_ = tid >> 2, o_ = (tid & 3) * 8;
            cpa16(bs_ + (STG_A + r_ * BKS + o_) * 2,
                  W + (size_t)(e0 + r_) * 512 + kk + o_);
        }
        asm volatile("cp.async.commit_group;");
    };

    load_stage(0, 0);
    load_stage(1, 32);

    int s_cur = 0, s_pref = 2;
    for (int kc = 0; kc < 16; kc++) {
        asm volatile("cp.async.wait_group 1;" ::: "memory");
        __syncthreads();
        if (kc + 2 < 16) { load_stage(s_pref, (kc + 2) * 32); }
        else { asm volatile("cp.async.commit_group;"); }
        if (++s_pref == NSTG) s_pref = 0;

        const uint32_t bs = sb + s_cur * (STG_TOT * 2);
        if (++s_cur == NSTG) s_cur = 0;

        uint32_t a0[4], a1[4];
        ldsm4(a0, bs + (aR * BKS + aC) * 2);
        ldsm4(a1, bs + (aR * BKS + 16 + aC) * 2);
#pragma unroll
        for (int j = 0; j < 8; j++) {
            uint32_t bh[4];
            ldsm4(bh, bs + (STG_A + (j * 8 + bR) * BKS + bC) * 2);
            mma16816h(c[j], a0, bh[0], bh[1]);
            mma16816h(c[j], a1, bh[2], bh[3]);
        }
    }
}

// ---------------------------------------------------------------------------
// Q/K/V projection GEMM (grid.z selects)
// ---------------------------------------------------------------------------
__global__ __launch_bounds__(256, 2)
void gemm_qkv(const __half* __restrict__ Xq, const __half* __restrict__ Xk,
              const __half* __restrict__ Xv,
              const __half* __restrict__ Wq, const __half* __restrict__ Wk,
              const __half* __restrict__ Wv,
              const float* __restrict__ bq, const float* __restrict__ bk,
              const float* __restrict__ bv,
              __half* Qh, __half* Kh, __half* Vth)
{
    extern __shared__ __half smg[];
    const uint32_t sb = smem_u32(smg);
    const int tid = threadIdx.x, wid = tid >> 5, lane = tid & 31;
    const int m0 = blockIdx.y * 128, e0 = blockIdx.x * 64;
    const int z = blockIdx.z;
    const int g = lane >> 2, t2 = (lane & 3) * 2;

    const __half *A, *W;
    const float* bias;
    if (z == 0)      { A = Xq; W = Wq; bias = bq; }
    else if (z == 1) { A = Xk; W = Wk; bias = bk; }
    else             { A = Xv; W = Wv; bias = bv; }

    float c[8][4];
#pragma unroll
    for (int j = 0; j < 8; j++)
#pragma unroll
        for (int e = 0; e < 4; e++) c[j][e] = 0.f;

    gemm_core_h(A, W, m0, e0, sb, tid, c);

    const int r0 = m0 + wid * 16 + g;
    const int hh = e0 >> 6;
    if (z < 2) {
        const float scale = (z == 0) ? 0.125f : 1.0f;
        const int nn0 = r0 >> 2, bb2 = r0 & 3;
        __half* H = (z == 0 ? Qh : Kh) + ((size_t)(bb2 * HH + hh) * NQ + nn0) * 64;
#pragma unroll
        for (int j = 0; j < 8; j++) {
            const int d = j * 8 + t2;
            const int e = e0 + d;
            float b0 = bias[e], b1 = bias[e + 1];
            float v0 = (c[j][0] + b0) * scale, v1 = (c[j][1] + b1) * scale;
            float v2 = (c[j][2] + b0) * scale, v3 = (c[j][3] + b1) * scale;
            *(uint32_t*)(H + d)          = pkh(v0, v1);
            *(uint32_t*)(H + 2 * 64 + d) = pkh(v2, v3);
        }
    } else {
        const int lv = r0 >> 2, bb2 = r0 & 3;
        __half* VH = Vth + (size_t)(bb2 * HH + hh) * HD * LK;
#pragma unroll
        for (int j = 0; j < 8; j++) {
            const int d = j * 8 + t2;
            float b0 = bias[e0 + d], b1 = bias[e0 + d + 1];
            float v0 = c[j][0] + b0, v1 = c[j][1] + b1;
            float v2 = c[j][2] + b0, v3 = c[j][3] + b1;
#pragma unroll
            for (int u = 0; u < 4; u++) {
                float val = (u == 0) ? v0 : (u == 1) ? v1 : (u == 2) ? v2 : v3;
                int dd = d + (u & 1);
                int ll = lv + ((u >> 1) * 2);
                VH[(size_t)dd * LK + ll] = __float2half_rn(val);
            }
        }
    }
}

// ---------------------------------------------------------------------------
// O projection GEMM (fp32 out, row-major)
// ---------------------------------------------------------------------------
__global__ __launch_bounds__(256, 2)
void gemm_o(const __half* __restrict__ A, const __half* __restrict__ W,
            const float* __restrict__ bias, float* __restrict__ Cf)
{
    extern __shared__ __half smg[];
    const uint32_t sb = smem_u32(smg);
    const int tid = threadIdx.x, wid = tid >> 5, lane = tid & 31;
    const int m0 = blockIdx.y * 128, e0 = blockIdx.x * 64;
    const int g = lane >> 2, t2 = (lane & 3) * 2;

    float c[8][4];
#pragma unroll
    for (int j = 0; j < 8; j++)
#pragma unroll
        for (int e = 0; e < 4; e++) c[j][e] = 0.f;

    gemm_core_h(A, W, m0, e0, sb, tid, c);

    const int r0 = m0 + wid * 16 + g, r8 = r0 + 8;
#pragma unroll
    for (int j = 0; j < 8; j++) {
        const int e = e0 + j * 8 + t2;
        float b0 = bias[e], b1 = bias[e + 1];
        *(float2*)(Cf + (size_t)r0 * 512 + e) = make_float2(c[j][0] + b0, c[j][1] + b1);
        *(float2*)(Cf + (size_t)r8 * 512 + e) = make_float2(c[j][2] + b0, c[j][3] + b1);
    }
}

// ---------------------------------------------------------------------------
// Flash attention, single-fp16, 32 q-rows/warp (fragment reuse), but back
// to 4 warps/CTA (128 q-rows) with __launch_bounds__(128,3): 12 warps/SM.
// ---------------------------------------------------------------------------
#define KSTR 72
#define ASTG 19200   // per-stage: Kh (9216) | Vh (9216) | pe2 (768)
#define ATTN_SMEM (2 * ASTG)

__global__ __launch_bounds__(128, 3)
void attn_kernel(const float* __restrict__ pe1, const float* __restrict__ pe2)
{
    extern __shared__ char smc[];
    const uint32_t sb = smem_u32(smc);
    const int tid  = threadIdx.x;
    const int wid  = tid >> 5;           // 0..3
    const int lane = tid & 31;
    const int g    = lane >> 2;
    const int t2   = (lane & 3) * 2;
    const int bR   = lane & 7;
    const int bC   = (lane >> 3) * 8;
    const int bh   = blockIdx.y;
    const int b    = bh >> 3, h = bh & 7;
    const int n0   = blockIdx.x * 128;
    const int rowB = n0 + wid * 32;      // this warp's 32-row base

    // ---- Q fragments for two m16 row-blocks ----
    uint32_t qhA[4][4], qhB[4][4];
    {
        const __half* Qp = g_Qh + (size_t)bh * NQ * HD;
        const size_t rA0 = (size_t)(rowB + g) * HD;
        const size_t rA8 = (size_t)(rowB + g + 8) * HD;
        const size_t rB0 = (size_t)(rowB + g + 16) * HD;
        const size_t rB8 = (size_t)(rowB + g + 24) * HD;
#pragma unroll
        for (int ks = 0; ks < 4; ks++) {
            qhA[ks][0] = *(const uint32_t*)(Qp + rA0 + ks * 16 + t2);
            qhA[ks][1] = *(const uint32_t*)(Qp + rA8 + ks * 16 + t2);
            qhA[ks][2] = *(const uint32_t*)(Qp + rA0 + ks * 16 + 8 + t2);
            qhA[ks][3] = *(const uint32_t*)(Qp + rA8 + ks * 16 + 8 + t2);
            qhB[ks][0] = *(const uint32_t*)(Qp + rB0 + ks * 16 + t2);
            qhB[ks][1] = *(const uint32_t*)(Qp + rB8 + ks * 16 + t2);
            qhB[ks][2] = *(const uint32_t*)(Qp + rB0 + ks * 16 + 8 + t2);
            qhB[ks][3] = *(const uint32_t*)(Qp + rB8 + ks * 16 + 8 + t2);
        }
    }
    float p1[4][3];   // rows g, g+8, g+16, g+24 (scaled 1/8)
#pragma unroll
    for (int rr = 0; rr < 4; rr++)
#pragma unroll
        for (int cc = 0; cc < 3; cc++)
            p1[rr][cc] = pe1[((size_t)b * NQ + rowB + g + rr * 8) * 3 + cc] * 0.125f;

    float oA[8][4], oB[8][4];
#pragma unroll
    for (int j = 0; j < 8; j++)
#pragma unroll
        for (int e = 0; e < 4; e++) { oA[j][e] = 0.f; oB[j][e] = 0.f; }
    float rs[4] = {0.f, 0.f, 0.f, 0.f};

    auto issue_tile = [&](int l0, uint32_t stb) {
#pragma unroll
        for (int q4 = 0; q4 < 4; q4++) {
            int idx = tid + q4 * 128;            // 0..511
            int r = idx >> 3, cchunk = idx & 7;
            size_t ko = ((size_t)bh * LK + l0 + r) * HD + cchunk * 8;
            size_t vo = ((size_t)bh * HD + r) * LK + l0 + cchunk * 8;
            uint32_t so = stb + r * (KSTR * 2) + cchunk * 16;
            cpa16(so,        g_Kh + ko);
            cpa16(so + 9216, g_Vth + vo);
        }
        if (tid < 48)
            cpa16(stb + 18432 + tid * 16, (const char*)pe2 + (size_t)l0 * 12 + tid * 16);
        asm volatile("cp.async.commit_group;");
    };

    issue_tile(0, sb);

    for (int lt = 0; lt < LK / 64; lt++) {
        const int stcur = lt & 1;
        if (lt < LK / 64 - 1) {
            issue_tile((lt + 1) * 64, sb + ((lt + 1) & 1) * ASTG);
            asm volatile("cp.async.wait_group 1;" ::: "memory");
        } else {
            asm volatile("cp.async.wait_group 0;" ::: "memory");
        }
        __syncthreads();

        const uint32_t stb = sb + stcur * ASTG;
        const uint32_t uKh = stb, uVh = stb + 9216;
        const float* sp2 = (const float*)(smc + stcur * ASTG + 18432);

        // ---- S = Qh·Kh + pe1·pe2 (both row-blocks share each K fragment) ----
        float sA[8][4], sB[8][4];
#pragma unroll
        for (int j = 0; j < 8; j++) {
            const int jc = j * 8 + t2;
            float e0 = sp2[jc * 3 + 0], e1 = sp2[jc * 3 + 1], e2 = sp2[jc * 3 + 2];
            float f0 = sp2[(jc + 1) * 3 + 0], f1 = sp2[(jc + 1) * 3 + 1], f2 = sp2[(jc + 1) * 3 + 2];
            sA[j][0] = p1[0][0] * e0 + p1[0][1] * e1 + p1[0][2] * e2;
            sA[j][1] = p1[0][0] * f0 + p1[0][1] * f1 + p1[0][2] * f2;
            sA[j][2] = p1[1][0] * e0 + p1[1][1] * e1 + p1[1][2] * e2;
            sA[j][3] = p1[1][0] * f0 + p1[1][1] * f1 + p1[1][2] * f2;
            sB[j][0] = p1[2][0] * e0 + p1[2][1] * e1 + p1[2][2] * e2;
            sB[j][1] = p1[2][0] * f0 + p1[2][1] * f1 + p1[2][2] * f2;
            sB[j][2] = p1[3][0] * e0 + p1[3][1] * e1 + p1[3][2] * e2;
            sB[j][3] = p1[3][0] * f0 + p1[3][1] * f1 + p1[3][2] * f2;

            uint32_t kh[8];
            const uint32_t rb = (uint32_t)((j * 8 + bR) * KSTR + bC) * 2;
            ldsm4(kh,     uKh + rb);
            ldsm4(kh + 4, uKh + rb + 64);
#pragma unroll
            for (int ks = 0; ks < 4; ks++) {
                mma16816h(sA[j], qhA[ks], kh[2 * ks], kh[2 * ks + 1]);
                mma16816h(sB[j], qhB[ks], kh[2 * ks], kh[2 * ks + 1]);
            }
        }

        // ---- softmax (no max subtraction; scores bounded) ----
#pragma unroll
        for (int j = 0; j < 8; j++) {
            sA[j][0] = __expf(sA[j][0]); sA[j][1] = __expf(sA[j][1]);
            sA[j][2] = __expf(sA[j][2]); sA[j][3] = __expf(sA[j][3]);
            sB[j][0] = __expf(sB[j][0]); sB[j][1] = __expf(sB[j][1]);
            sB[j][2] = __expf(sB[j][2]); sB[j][3] = __expf(sB[j][3]);
            rs[0] += sA[j][0] + sA[j][1];
            rs[1] += sA[j][2] + sA[j][3];
            rs[2] += sB[j][0] + sB[j][1];
            rs[3] += sB[j][2] + sB[j][3];
        }

        // ---- P fragments (single fp16) ----
        uint32_t phA[4][4], phB[4][4];
#pragma unroll
        for (int ks = 0; ks < 4; ks++) {
            phA[ks][0] = pkh(sA[2 * ks][0], sA[2 * ks][1]);
            phA[ks][1] = pkh(sA[2 * ks][2], sA[2 * ks][3]);
            phA[ks][2] = pkh(sA[2 * ks + 1][0], sA[2 * ks + 1][1]);
            phA[ks][3] = pkh(sA[2 * ks + 1][2], sA[2 * ks + 1][3]);
            phB[ks][0] = pkh(sB[2 * ks][0], sB[2 * ks][1]);
            phB[ks][1] = pkh(sB[2 * ks][2], sB[2 * ks][3]);
            phB[ks][2] = pkh(sB[2 * ks + 1][0], sB[2 * ks + 1][1]);
            phB[ks][3] = pkh(sB[2 * ks + 1][2], sB[2 * ks + 1][3]);
        }

        // ---- O += Ph·Vh (both row-blocks share each V fragment) ----
#pragma unroll
        for (int j = 0; j < 8; j++) {
            uint32_t vh[8];
            const uint32_t rb = (uint32_t)((j * 8 + bR) * KSTR + bC) * 2;
            ldsm4(vh,     uVh + rb);
            ldsm4(vh + 4, uVh + rb + 64);
#pragma unroll
            for (int ks = 0; ks < 4; ks++) {
                mma16816h(oA[j], phA[ks], vh[2 * ks], vh[2 * ks + 1]);
                mma16816h(oB[j], phB[ks], vh[2 * ks], vh[2 * ks + 1]);
            }
        }
        __syncthreads();
    }

    // ---- epilogue ----
#pragma unroll
    for (int rr = 0; rr < 4; rr++) {
        rs[rr] += __shfl_xor_sync(0xffffffffu, rs[rr], 1);
        rs[rr] += __shfl_xor_sync(0xffffffffu, rs[rr], 2);
    }
    const float i0 = 1.f / rs[0], i8 = 1.f / rs[1];
    const float i16 = 1.f / rs[2], i24 = 1.f / rs[3];

    const size_t d0  = ((size_t)(rowB + g)      * BB + b) * EMBED + h * HD + t2;
    const size_t d8  = ((size_t)(rowB + g + 8)  * BB + b) * EMBED + h * HD + t2;
    const size_t d16 = ((size_t)(rowB + g + 16) * BB + b) * EMBED + h * HD + t2;
    const size_t d24 = ((size_t)(rowB + g + 24) * BB + b) * EMBED + h * HD + t2;
#pragma unroll
    for (int j = 0; j < 8; j++) {
        *(uint32_t*)(g_Ath + d0  + j * 8) = pkh(oA[j][0] * i0,  oA[j][1] * i0);
        *(uint32_t*)(g_Ath + d8  + j * 8) = pkh(oA[j][2] * i8,  oA[j][3] * i8);
        *(uint32_t*)(g_Ath + d16 + j * 8) = pkh(oB[j][0] * i16, oB[j][1] * i16);
        *(uint32_t*)(g_Ath + d24 + j * 8) = pkh(oB[j][2] * i24, oB[j][3] * i24);
    }
}

// ---------------------------------------------------------------------------
extern "C" void kernel_launch(void* const* d_in, const int* in_sizes, int n_in,
                              void* d_out, int out_size)
{
    const float* q   = (const float*)d_in[0];
    const float* k   = (const float*)d_in[1];
    const float* v   = (const float*)d_in[2];
    const float* pe1 = (const float*)d_in[3];
    const float* pe2 = (const float*)d_in[4];
    const float* Wq  = (const float*)d_in[5];
    const float* bq  = (const float*)d_in[6];
    const float* Wk  = (const float*)d_in[7];
    const float* bk  = (const float*)d_in[8];
    const float* Wv  = (const float*)d_in[9];
    const float* bv  = (const float*)d_in[10];
    const float* Wo  = (const float*)d_in[11];
    const float* bo  = (const float*)d_in[12];
    float* out = (float*)d_out;

    cudaFuncSetAttribute(gemm_qkv, cudaFuncAttributeMaxDynamicSharedMemorySize, GEMM_SMEM);
    cudaFuncSetAttribute(gemm_o, cudaFuncAttributeMaxDynamicSharedMemorySize, GEMM_SMEM);
    cudaFuncSetAttribute(attn_kernel, cudaFuncAttributeMaxDynamicSharedMemorySize, ATTN_SMEM);

    __half *Xq, *Xk, *Xv, *hWq, *hWk, *hWv, *hWo;
    __half *Qh, *Kh, *Vth, *Ath;
    cudaGetSymbolAddress((void**)&Xq, g_Xq);
    cudaGetSymbolAddress((void**)&Xk, g_Xk);
    cudaGetSymbolAddress((void**)&Xv, g_Xv);
    cudaGetSymbolAddress((void**)&hWq, g_Wq);
    cudaGetSymbolAddress((void**)&hWk, g_Wk);
    cudaGetSymbolAddress((void**)&hWv, g_Wv);
    cudaGetSymbolAddress((void**)&hWo, g_Wo);
    cudaGetSymbolAddress((void**)&Qh, g_Qh);
    cudaGetSymbolAddress((void**)&Kh, g_Kh);
    cudaGetSymbolAddress((void**)&Vth, g_Vth);
    cudaGetSymbolAddress((void**)&Ath, g_Ath);

    splitX<<<dim3(4096, 3), 256>>>(q, k, v, Xq, Xk, Xv);                            // 1
    splitW<<<dim3(256, 4), 256>>>(Wq, Wk, Wv, Wo, hWq, hWk, hWv, hWo);              // 2
    gemm_qkv<<<dim3(8, 64, 3), 256, GEMM_SMEM>>>(
        Xq, Xk, Xv, hWq, hWk, hWv, bq, bk, bv, Qh, Kh, Vth);                        // 3
    attn_kernel<<<dim3(16, 32), 128, ATTN_SMEM>>>(pe1, pe2);                        // 4 (profiled)
    gemm_o<<<dim3(8, 64), 256, GEMM_SMEM>>>(Ath, hWo, bo, out);                     // 5
}

// round 17
// speedup vs baseline: 1.2028x; 1.1757x over previous
#include <cuda_runtime.h>
#include <cuda_bf16.h>
#include <cuda_fp16.h>
#include <stdint.h>
#include <math.h>

#define EMBED 512
#define HH    8
#define HD    64
#define NQ    2048
#define LK    2048
#define BB    4
#define MROWS (NQ * BB)
#define NELEM ((size_t)MROWS * EMBED)
#define WELEM ((size_t)EMBED * EMBED)

// ---------------- device scratch (allocation-free rule) --------------------
__device__ __align__(256) __half g_Xq[NELEM], g_Xk[NELEM], g_Xv[NELEM];
__device__ __align__(256) __half g_Wq[WELEM], g_Wk[WELEM];
__device__ __align__(256) __half g_Wv[WELEM], g_Wo[WELEM];
__device__ __align__(256) __half g_Qh[NELEM];    // [bh][n][64], x1/8
__device__ __align__(256) __half g_Kh[NELEM];    // [bh][l][64]
__device__ __align__(256) __half g_Vth[NELEM];   // [bh][d][L]
__device__ __align__(256) __half g_Ath[NELEM];   // [r][512]

// ---------------- helpers ---------------------------------------------------
__device__ __forceinline__ uint32_t smem_u32(const void* p) {
    uint32_t a;
    asm("{ .reg .u64 t; cvta.to.shared.u64 t, %1; cvt.u32.u64 %0, t; }"
        : "=r"(a) : "l"(p));
    return a;
}
__device__ __forceinline__ uint32_t pkh(float a, float b) {
    __half2 h = __floats2half2_rn(a, b);
    return *reinterpret_cast<uint32_t*>(&h);
}
__device__ __forceinline__ void mma16816h(float* c, const uint32_t* a,
                                          uint32_t b0, uint32_t b1) {
    asm volatile(
        "mma.sync.aligned.m16n8k16.row.col.f32.f16.f16.f32 "
        "{%0,%1,%2,%3}, {%4,%5,%6,%7}, {%8,%9}, {%0,%1,%2,%3};"
        : "+f"(c[0]), "+f"(c[1]), "+f"(c[2]), "+f"(c[3])
        : "r"(a[0]), "r"(a[1]), "r"(a[2]), "r"(a[3]), "r"(b0), "r"(b1));
}
__device__ __forceinline__ void ldsm4(uint32_t* r, uint32_t addr) {
    asm volatile("ldmatrix.sync.aligned.m8n8.x4.shared.b16 {%0,%1,%2,%3}, [%4];"
                 : "=r"(r[0]), "=r"(r[1]), "=r"(r[2]), "=r"(r[3]) : "r"(addr));
}
__device__ __forceinline__ void cpa16(uint32_t s, const void* g) {
    asm volatile("cp.async.cg.shared.global [%0], [%1], 16;" :: "r"(s), "l"(g));
}

// ---------------------------------------------------------------------------
// merged split kernel: fp32 -> single fp16 for X (q,k,v) and W (q,k,v,o).
// blocks [0, 12288): X in 3 chunks of 4096; [12288, 13312): W in 4 chunks of 256.
// ---------------------------------------------------------------------------
__global__ __launch_bounds__(256)
void split_all(const float* __restrict__ q, const float* __restrict__ k,
               const float* __restrict__ v,
               const float* __restrict__ wq, const float* __restrict__ wk,
               const float* __restrict__ wv, const float* __restrict__ wo,
               __half* xq, __half* xk, __half* xv,
               __half* dq, __half* dk, __half* dv, __half* dw)
{
    const float* src; __half* dst; size_t i;
    int bx = blockIdx.x;
    if (bx < 12288) {
        int part = bx >> 12;              // /4096
        int blk  = bx & 4095;
        if (part == 0)      { src = q; dst = xq; }
        else if (part == 1) { src = k; dst = xk; }
        else                { src = v; dst = xv; }
        i = (size_t)blk * 256 + threadIdx.x;
    } else {
        int wb = bx - 12288;
        int part = wb >> 8;               // /256
        int blk  = wb & 255;
        if (part == 0)      { src = wq; dst = dq; }
        else if (part == 1) { src = wk; dst = dk; }
        else if (part == 2) { src = wv; dst = dv; }
        else                { src = wo; dst = dw; }
        i = (size_t)blk * 256 + threadIdx.x;
    }
    float4 x = ((const float4*)src)[i];
    ((uint2*)dst)[i] = make_uint2(pkh(x.x, x.y), pkh(x.z, x.w));
}

// ---------------------------------------------------------------------------
// fp16 single x single GEMM core: 128m x 64n tile, BK=32, 3-stage pipeline.
// ---------------------------------------------------------------------------
#define BKS   40
#define STG_A (128 * BKS)
#define STG_W (64 * BKS)
#define STG_TOT (STG_A + STG_W)
#define NSTG  3
#define GEMM_SMEM (NSTG * STG_TOT * 2)

__device__ __forceinline__ void gemm_core_h(
    const __half* __restrict__ A, const __half* __restrict__ W,
    int m0, int e0, uint32_t sb, int tid, float c[8][4])
{
    const int wid = tid >> 5, lane = tid & 31;
    const int wrow = wid * 16;
    const int aR = wrow + (lane & 7) + ((lane >> 3) & 1) * 8;
    const int aC = (lane >> 4) * 8;
    const int bR = lane & 7, bC = (lane >> 3) * 8;

    auto load_stage = [&](int s, int kk) {
        uint32_t bs_ = sb + s * (STG_TOT * 2);
#pragma unroll
        for (int ch = tid; ch < 512; ch += 256) {
            int r_ = ch >> 2, o_ = (ch & 3) * 8;
            cpa16(bs_ + (r_ * BKS + o_) * 2, A + (size_t)(m0 + r_) * 512 + kk + o_);
        }
        {
            int r_ = tid >> 2, o_ = (tid & 3) * 8;
            cpa16(bs_ + (STG_A + r_ * BKS + o_) * 2,
                  W + (size_t)(e0 + r_) * 512 + kk + o_);
        }
        asm volatile("cp.async.commit_group;");
    };

    load_stage(0, 0);
    load_stage(1, 32);

    int s_cur = 0, s_pref = 2;
    for (int kc = 0; kc < 16; kc++) {
        asm volatile("cp.async.wait_group 1;" ::: "memory");
        __syncthreads();
        if (kc + 2 < 16) { load_stage(s_pref, (kc + 2) * 32); }
        else { asm volatile("cp.async.commit_group;"); }
        if (++s_pref == NSTG) s_pref = 0;

        const uint32_t bs = sb + s_cur * (STG_TOT * 2);
        if (++s_cur == NSTG) s_cur = 0;

        uint32_t a0[4], a1[4];
        ldsm4(a0, bs + (aR * BKS + aC) * 2);
        ldsm4(a1, bs + (aR * BKS + 16 + aC) * 2);
#pragma unroll
        for (int j = 0; j < 8; j++) {
            uint32_t bh[4];
            ldsm4(bh, bs + (STG_A + (j * 8 + bR) * BKS + bC) * 2);
            mma16816h(c[j], a0, bh[0], bh[1]);
            mma16816h(c[j], a1, bh[2], bh[3]);
        }
    }
}

// ---------------------------------------------------------------------------
// Q/K/V projection GEMM (grid.z selects)
// ---------------------------------------------------------------------------
__global__ __launch_bounds__(256, 2)
void gemm_qkv(const __half* __restrict__ Xq, const __half* __restrict__ Xk,
              const __half* __restrict__ Xv,
              const __half* __restrict__ Wq, const __half* __restrict__ Wk,
              const __half* __restrict__ Wv,
              const float* __restrict__ bq, const float* __restrict__ bk,
              const float* __restrict__ bv,
              __half* Qh, __half* Kh, __half* Vth)
{
    extern __shared__ __half smg[];
    const uint32_t sb = smem_u32(smg);
    const int tid = threadIdx.x, wid = tid >> 5, lane = tid & 31;
    const int m0 = blockIdx.y * 128, e0 = blockIdx.x * 64;
    const int z = blockIdx.z;
    const int g = lane >> 2, t2 = (lane & 3) * 2;

    const __half *A, *W;
    const float* bias;
    if (z == 0)      { A = Xq; W = Wq; bias = bq; }
    else if (z == 1) { A = Xk; W = Wk; bias = bk; }
    else             { A = Xv; W = Wv; bias = bv; }

    float c[8][4];
#pragma unroll
    for (int j = 0; j < 8; j++)
#pragma unroll
        for (int e = 0; e < 4; e++) c[j][e] = 0.f;

    gemm_core_h(A, W, m0, e0, sb, tid, c);

    const int r0 = m0 + wid * 16 + g;
    const int hh = e0 >> 6;
    if (z < 2) {
        const float scale = (z == 0) ? 0.125f : 1.0f;
        const int nn0 = r0 >> 2, bb2 = r0 & 3;
        __half* H = (z == 0 ? Qh : Kh) + ((size_t)(bb2 * HH + hh) * NQ + nn0) * 64;
#pragma unroll
        for (int j = 0; j < 8; j++) {
            const int d = j * 8 + t2;
            const int e = e0 + d;
            float b0 = bias[e], b1 = bias[e + 1];
            float v0 = (c[j][0] + b0) * scale, v1 = (c[j][1] + b1) * scale;
            float v2 = (c[j][2] + b0) * scale, v3 = (c[j][3] + b1) * scale;
            *(uint32_t*)(H + d)          = pkh(v0, v1);
            *(uint32_t*)(H + 2 * 64 + d) = pkh(v2, v3);
        }
    } else {
        const int lv = r0 >> 2, bb2 = r0 & 3;
        __half* VH = Vth + (size_t)(bb2 * HH + hh) * HD * LK;
#pragma unroll
        for (int j = 0; j < 8; j++) {
            const int d = j * 8 + t2;
            float b0 = bias[e0 + d], b1 = bias[e0 + d + 1];
            float v0 = c[j][0] + b0, v1 = c[j][1] + b1;
            float v2 = c[j][2] + b0, v3 = c[j][3] + b1;
#pragma unroll
            for (int u = 0; u < 4; u++) {
                float val = (u == 0) ? v0 : (u == 1) ? v1 : (u == 2) ? v2 : v3;
                int dd = d + (u & 1);
                int ll = lv + ((u >> 1) * 2);
                VH[(size_t)dd * LK + ll] = __float2half_rn(val);
            }
        }
    }
}

// ---------------------------------------------------------------------------
// O projection GEMM (fp32 out, row-major)
// ---------------------------------------------------------------------------
__global__ __launch_bounds__(256, 2)
void gemm_o(const __half* __restrict__ A, const __half* __restrict__ W,
            const float* __restrict__ bias, float* __restrict__ Cf)
{
    extern __shared__ __half smg[];
    const uint32_t sb = smem_u32(smg);
    const int tid = threadIdx.x, wid = tid >> 5, lane = tid & 31;
    const int m0 = blockIdx.y * 128, e0 = blockIdx.x * 64;
    const int g = lane >> 2, t2 = (lane & 3) * 2;

    float c[8][4];
#pragma unroll
    for (int j = 0; j < 8; j++)
#pragma unroll
        for (int e = 0; e < 4; e++) c[j][e] = 0.f;

    gemm_core_h(A, W, m0, e0, sb, tid, c);

    const int r0 = m0 + wid * 16 + g, r8 = r0 + 8;
#pragma unroll
    for (int j = 0; j < 8; j++) {
        const int e = e0 + j * 8 + t2;
        float b0 = bias[e], b1 = bias[e + 1];
        *(float2*)(Cf + (size_t)r0 * 512 + e) = make_float2(c[j][0] + b0, c[j][1] + b1);
        *(float2*)(Cf + (size_t)r8 * 512 + e) = make_float2(c[j][2] + b0, c[j][3] + b1);
    }
}

// ---------------------------------------------------------------------------
// Flash attention — EXACT R14 configuration (best measured: 124.9 us).
// Pure single-fp16: S = Qh·Kh + pe, O = Ph·Vh. 4 warps x 16 q-rows,
// __launch_bounds__(128,3), 64-key double-buffered tiles, grid 1024.
// ---------------------------------------------------------------------------
#define KSTR 72
#define ASTG 19200   // per-stage: Kh (9216) | Vh (9216) | pe2 (768)
#define ATTN_SMEM (2 * ASTG)

__global__ __launch_bounds__(128, 3)
void attn_kernel(const float* __restrict__ pe1, const float* __restrict__ pe2)
{
    extern __shared__ char smc[];
    const uint32_t sb = smem_u32(smc);
    const int tid  = threadIdx.x;
    const int wid  = tid >> 5;
    const int lane = tid & 31;
    const int g    = lane >> 2;
    const int t2   = (lane & 3) * 2;
    const int bR   = lane & 7;
    const int bC   = (lane >> 3) * 8;
    const int bh   = blockIdx.y;
    const int b    = bh >> 3, h = bh & 7;
    const int n0   = blockIdx.x * 64;
    const int rowB = n0 + wid * 16;

    // ---- Q fragments (single fp16, resident all kernel) ----
    uint32_t qh[4][4];
    {
        const __half* Qp = g_Qh + (size_t)bh * NQ * HD;
        const size_t r0o = (size_t)(rowB + g) * HD;
        const size_t r8o = (size_t)(rowB + g + 8) * HD;
#pragma unroll
        for (int ks = 0; ks < 4; ks++) {
            qh[ks][0] = *(const uint32_t*)(Qp + r0o + ks * 16 + t2);
            qh[ks][1] = *(const uint32_t*)(Qp + r8o + ks * 16 + t2);
            qh[ks][2] = *(const uint32_t*)(Qp + r0o + ks * 16 + 8 + t2);
            qh[ks][3] = *(const uint32_t*)(Qp + r8o + ks * 16 + 8 + t2);
        }
    }
    float p1a[3], p1b[3];
#pragma unroll
    for (int cc = 0; cc < 3; cc++) {
        p1a[cc] = pe1[((size_t)b * NQ + rowB + g) * 3 + cc] * 0.125f;
        p1b[cc] = pe1[((size_t)b * NQ + rowB + g + 8) * 3 + cc] * 0.125f;
    }

    float o[8][4];
#pragma unroll
    for (int j = 0; j < 8; j++)
#pragma unroll
        for (int e = 0; e < 4; e++) o[j][e] = 0.f;
    float rs0 = 0.f, rs8 = 0.f;

    auto issue_tile = [&](int l0, uint32_t stb) {
#pragma unroll
        for (int half_ = 0; half_ < 4; half_++) {
            int idx = tid + half_ * 128;         // 0..511
            int r = idx >> 3, cchunk = idx & 7;
            size_t ko = ((size_t)bh * LK + l0 + r) * HD + cchunk * 8;
            size_t vo = ((size_t)bh * HD + r) * LK + l0 + cchunk * 8;
            uint32_t so = stb + r * (KSTR * 2) + cchunk * 16;
            cpa16(so,        g_Kh + ko);
            cpa16(so + 9216, g_Vth + vo);
        }
        if (tid < 48)
            cpa16(stb + 18432 + tid * 16, (const char*)pe2 + (size_t)l0 * 12 + tid * 16);
        asm volatile("cp.async.commit_group;");
    };

    issue_tile(0, sb);

    for (int lt = 0; lt < LK / 64; lt++) {
        const int stcur = lt & 1;
        if (lt < LK / 64 - 1) {
            issue_tile((lt + 1) * 64, sb + ((lt + 1) & 1) * ASTG);
            asm volatile("cp.async.wait_group 1;" ::: "memory");
        } else {
            asm volatile("cp.async.wait_group 0;" ::: "memory");
        }
        __syncthreads();

        const uint32_t stb = sb + stcur * ASTG;
        const uint32_t uKh = stb, uVh = stb + 9216;
        const float* sp2 = (const float*)(smc + stcur * ASTG + 18432);

        // ---- S = Qh·Kh + pe1·pe2 ----
        float s[8][4];
#pragma unroll
        for (int j = 0; j < 8; j++) {
            const int jc = j * 8 + t2;
            float e0 = sp2[jc * 3 + 0], e1 = sp2[jc * 3 + 1], e2 = sp2[jc * 3 + 2];
            float f0 = sp2[(jc + 1) * 3 + 0], f1 = sp2[(jc + 1) * 3 + 1], f2 = sp2[(jc + 1) * 3 + 2];
            s[j][0] = p1a[0] * e0 + p1a[1] * e1 + p1a[2] * e2;
            s[j][1] = p1a[0] * f0 + p1a[1] * f1 + p1a[2] * f2;
            s[j][2] = p1b[0] * e0 + p1b[1] * e1 + p1b[2] * e2;
            s[j][3] = p1b[0] * f0 + p1b[1] * f1 + p1b[2] * f2;

            uint32_t kh[8];
            const uint32_t rb = (uint32_t)((j * 8 + bR) * KSTR + bC) * 2;
            ldsm4(kh,     uKh + rb);
            ldsm4(kh + 4, uKh + rb + 64);
#pragma unroll
            for (int ks = 0; ks < 4; ks++)
                mma16816h(s[j], qh[ks], kh[2 * ks], kh[2 * ks + 1]);
        }

        // ---- softmax (no max subtraction; scores bounded) ----
#pragma unroll
        for (int j = 0; j < 8; j++) {
            s[j][0] = __expf(s[j][0]);
            s[j][1] = __expf(s[j][1]);
            s[j][2] = __expf(s[j][2]);
            s[j][3] = __expf(s[j][3]);
            rs0 += s[j][0] + s[j][1];
            rs8 += s[j][2] + s[j][3];
        }

        // ---- P fragments (single fp16) ----
        uint32_t ph[4][4];
#pragma unroll
        for (int ks = 0; ks < 4; ks++) {
            ph[ks][0] = pkh(s[2 * ks][0], s[2 * ks][1]);
            ph[ks][1] = pkh(s[2 * ks][2], s[2 * ks][3]);
            ph[ks][2] = pkh(s[2 * ks + 1][0], s[2 * ks + 1][1]);
            ph[ks][3] = pkh(s[2 * ks + 1][2], s[2 * ks + 1][3]);
        }

        // ---- O += Ph·Vh ----
#pragma unroll
        for (int j = 0; j < 8; j++) {
            uint32_t vh[8];
            const uint32_t rb = (uint32_t)((j * 8 + bR) * KSTR + bC) * 2;
            ldsm4(vh,     uVh + rb);
            ldsm4(vh + 4, uVh + rb + 64);
#pragma unroll
            for (int ks = 0; ks < 4; ks++)
                mma16816h(o[j], ph[ks], vh[2 * ks], vh[2 * ks + 1]);
        }
        __syncthreads();
    }

    // ---- epilogue: normalize, write single fp16 for O-GEMM ----
    rs0 += __shfl_xor_sync(0xffffffffu, rs0, 1);
    rs0 += __shfl_xor_sync(0xffffffffu, rs0, 2);
    rs8 += __shfl_xor_sync(0xffffffffu, rs8, 1);
    rs8 += __shfl_xor_sync(0xffffffffu, rs8, 2);
    const float inv0 = 1.f / rs0;
    const float inv8 = 1.f / rs8;

    const size_t d0 = ((size_t)(rowB + g) * BB + b) * EMBED + h * HD + t2;
    const size_t d8 = ((size_t)(rowB + g + 8) * BB + b) * EMBED + h * HD + t2;
#pragma unroll
    for (int j = 0; j < 8; j++) {
        *(uint32_t*)(g_Ath + d0 + j * 8) = pkh(o[j][0] * inv0, o[j][1] * inv0);
        *(uint32_t*)(g_Ath + d8 + j * 8) = pkh(o[j][2] * inv8, o[j][3] * inv8);
    }
}

// ---------------------------------------------------------------------------
extern "C" void kernel_launch(void* const* d_in, const int* in_sizes, int n_in,
                              void* d_out, int out_size)
{
    const float* q   = (const float*)d_in[0];
    const float* k   = (const float*)d_in[1];
    const float* v   = (const float*)d_in[2];
    const float* pe1 = (const float*)d_in[3];
    const float* pe2 = (const float*)d_in[4];
    const float* Wq  = (const float*)d_in[5];
    const float* bq  = (const float*)d_in[6];
    const float* Wk  = (const float*)d_in[7];
    const float* bk  = (const float*)d_in[8];
    const float* Wv  = (const float*)d_in[9];
    const float* bv  = (const float*)d_in[10];
    const float* Wo  = (const float*)d_in[11];
    const float* bo  = (const float*)d_in[12];
    float* out = (float*)d_out;

    cudaFuncSetAttribute(gemm_qkv, cudaFuncAttributeMaxDynamicSharedMemorySize, GEMM_SMEM);
    cudaFuncSetAttribute(gemm_o, cudaFuncAttributeMaxDynamicSharedMemorySize, GEMM_SMEM);
    cudaFuncSetAttribute(attn_kernel, cudaFuncAttributeMaxDynamicSharedMemorySize, ATTN_SMEM);

    __half *Xq, *Xk, *Xv, *hWq, *hWk, *hWv, *hWo;
    __half *Qh, *Kh, *Vth, *Ath;
    cudaGetSymbolAddress((void**)&Xq, g_Xq);
    cudaGetSymbolAddress((void**)&Xk, g_Xk);
    cudaGetSymbolAddress((void**)&Xv, g_Xv);
    cudaGetSymbolAddress((void**)&hWq, g_Wq);
    cudaGetSymbolAddress((void**)&hWk, g_Wk);
    cudaGetSymbolAddress((void**)&hWv, g_Wv);
    cudaGetSymbolAddress((void**)&hWo, g_Wo);
    cudaGetSymbolAddress((void**)&Qh, g_Qh);
    cudaGetSymbolAddress((void**)&Kh, g_Kh);
    cudaGetSymbolAddress((void**)&Vth, g_Vth);
    cudaGetSymbolAddress((void**)&Ath, g_Ath);

    split_all<<<13312, 256>>>(q, k, v, Wq, Wk, Wv, Wo,
                              Xq, Xk, Xv, hWq, hWk, hWv, hWo);                      // 1
    gemm_qkv<<<dim3(8, 64, 3), 256, GEMM_SMEM>>>(
        Xq, Xk, Xv, hWq, hWk, hWv, bq, bk, bv, Qh, Kh, Vth);                        // 2
    attn_kernel<<<dim3(32, 32), 128, ATTN_SMEM>>>(pe1, pe2);                        // 3
    gemm_o<<<dim3(8, 64), 256, GEMM_SMEM>>>(Ath, hWo, bo, out);                     // 4 (profiled)
}